// round 15
// baseline (speedup 1.0000x reference)
#include <cuda_runtime.h>
#include <cuda_bf16.h>
#include <math.h>
#include <stdint.h>

#define NB 32
#define NH 128
#define HID 5120
#define QLR 1536
#define KVLR 512
#define KVLEN 4096
#define CKVD 576
#define QHD 192

// ----------------------- device scratch (no allocs allowed) -----------------
__device__ __align__(16) float g_qa[NB * QLR];
__device__ __align__(16) float g_q[NB * NH * QHD];
__device__ __align__(16) float g_query[NB * NH * CKVD];
__device__ __align__(16) float g_scores[(size_t)NB * NH * KVLEN];   // 64 MB
__device__ __align__(16) float g_attn[NB * NH * KVLR];
__device__ __align__(16) float g_o[NB * NH * 128];

__device__ __align__(16) __nv_bfloat16 g_hqH[NB * HID],        g_hqL[NB * HID];
__device__ __align__(16) __nv_bfloat16 g_qanH[NB * QLR],       g_qanL[NB * QLR];
__device__ __align__(16) __nv_bfloat16 g_qH[NB * NH * QHD],    g_qL[NB * NH * QHD];
__device__ __align__(16) __nv_bfloat16 g_qryH[NB * NH * CKVD], g_qryL[NB * NH * CKVD];
__device__ __align__(16) __nv_bfloat16 g_prH[(size_t)NB * NH * KVLEN];
__device__ __align__(16) __nv_bfloat16 g_prL[(size_t)NB * NH * KVLEN];
__device__ __align__(16) __nv_bfloat16 g_atH[NB * NH * KVLR],  g_atL[NB * NH * KVLR];
__device__ __align__(16) __nv_bfloat16 g_oH[NB * NH * 128],    g_oL[NB * NH * 128];

// ----------------------- helpers -------------------------------------------
__device__ __forceinline__ void mma_bf16(float* c, const uint32_t* a, const uint32_t* b) {
    asm volatile(
        "mma.sync.aligned.m16n8k16.row.col.f32.bf16.bf16.f32 "
        "{%0,%1,%2,%3},{%4,%5,%6,%7},{%8,%9},{%0,%1,%2,%3};\n"
        : "+f"(c[0]), "+f"(c[1]), "+f"(c[2]), "+f"(c[3])
        : "r"(a[0]), "r"(a[1]), "r"(a[2]), "r"(a[3]), "r"(b[0]), "r"(b[1]));
}
// pack 2 fp32 -> bf16x2 hi (a in low half) + residual bf16x2
__device__ __forceinline__ void cvt2(float a, float b, uint32_t& H, uint32_t& L) {
    asm("cvt.rn.satfinite.bf16x2.f32 %0, %1, %2;" : "=r"(H) : "f"(b), "f"(a));
    float ha = __uint_as_float(H << 16);
    float hb = __uint_as_float(H & 0xffff0000u);
    asm("cvt.rn.satfinite.bf16x2.f32 %0, %1, %2;" : "=r"(L) : "f"(b - hb), "f"(a - ha));
}
__device__ __forceinline__ uint32_t smem_u32(const void* p) {
    uint32_t a;
    asm("{ .reg .u64 t; cvta.to.shared.u64 t, %1; cvt.u32.u64 %0, t; }"
        : "=r"(a) : "l"(p));
    return a;
}
__device__ __forceinline__ void cpasync(uint32_t s, const void* g) {
    asm volatile("cp.async.cg.shared.global [%0],[%1],16;" :: "r"(s), "l"(g) : "memory");
}
#define CP_COMMIT() asm volatile("cp.async.commit_group;" ::: "memory")
#define LDSM4(r, ad) \
    asm volatile("ldmatrix.sync.aligned.m8n8.x4.shared.b16 {%0,%1,%2,%3},[%4];" \
        : "=r"((r)[0]), "=r"((r)[1]), "=r"((r)[2]), "=r"((r)[3]) : "r"(ad))
#define LDSM4T(r, ad) \
    asm volatile("ldmatrix.sync.aligned.m8n8.x4.trans.shared.b16 {%0,%1,%2,%3},[%4];" \
        : "=r"((r)[0]), "=r"((r)[1]), "=r"((r)[2]), "=r"((r)[3]) : "r"(ad))

// ---------------------------------------------------------------------------
// Unified GEMM: A = pre-split bf16 hi/lo planes; B = fp32 gmem, staged via
// cp.async and converted to bf16 hi/lo IN PLACE in smem (thread-local regions).
// C fp32 = alpha * 3-pass (aH*bH + aH*bL + aL*bH).
//   BT=false (NT): B is [n][k] fp32 rows.   BT=true (NN): B is [k][n] fp32 rows.
// CTA tile TM x 128, KC=64, 256 threads, 3-stage pipeline.
// grid.x = N/128, grid.y = batch (ptr strides), grid.z = split-K (AT->atomics).
//
// B smem layout per stage (in-place convert):
//   NT: row n (256B): fp32 k0..63 -> [H k0-31 |L k0-31 |H k32-63 |L k32-63] x64B
//   BT: row k (512B): fp32 n0..127 -> 4 x [H n32 |L n32] blocks of 128B
//   16B chunks XOR-swizzled by ((row&3)<<4) in both write and read paths.
// ---------------------------------------------------------------------------
template <int TM, bool BT, bool AT>
__global__ __launch_bounds__(256, 1) void cgemm(
    const __nv_bfloat16* __restrict__ AH, const __nv_bfloat16* __restrict__ AL,
    int lda, int sA,
    const float* __restrict__ B, int ldb, int sB,
    float* __restrict__ C, int ldc, int sC,
    int K, float alpha)
{
    constexpr int ABYTES = TM * 128;            // one A plane
    constexpr int BOFF   = TM * 256;            // B offset in stage
    constexpr int STAGE  = TM * 256 + 32768;
    constexpr int MS = (TM == 128) ? 2 : 1;
    constexpr int NS = (TM == 128) ? 8 : 4;

    extern __shared__ __align__(1024) char sm[];
    const uint32_t sb = smem_u32(sm);
    const int tid = threadIdx.x, lane = tid & 31, warp = tid >> 5;

    const __nv_bfloat16* AHb = AH + (size_t)blockIdx.y * sA;
    const __nv_bfloat16* ALb = AL + (size_t)blockIdx.y * sA;
    const float* Bb = B + (size_t)blockIdx.y * sB;
    float* Cb = C + (size_t)blockIdx.y * sC;

    const int n0 = blockIdx.x * 128;
    const int kseg = K / (int)gridDim.z;
    const int kst = blockIdx.z * kseg;
    const int nslab = kseg >> 6;

    const int wm = (TM == 128) ? ((warp >> 1) * 32) : ((warp & 1) * 16);
    const int wn = (TM == 128) ? ((warp & 1) * 64) : ((warp >> 1) * 32);

    // B convert-region ownership (fixed per thread)
    const int br = BT ? (tid >> 2) : (tid >> 1);        // row (k-row or n-row)
    const int bq = BT ? (tid & 3) : (tid & 1);          // 128B sub-region
    const int bROW = BT ? 512 : 256;
    const int bsw = (br & 3) << 4;

    float acc[MS][NS][4];
#pragma unroll
    for (int i = 0; i < MS; i++)
#pragma unroll
        for (int j = 0; j < NS; j++)
#pragma unroll
            for (int q = 0; q < 4; q++) acc[i][j][q] = 0.0f;

    auto issue = [&](int s) {
        const int kp = kst + s * 64;
        const uint32_t st = sb + (s % 3) * STAGE;
        // A planes: TM x 64 bf16 each, 128B rows, swizzle ^((r&7)<<4)
#pragma unroll
        for (int i = 0; i < TM / 32; i++) {
            int lin = tid + i * 256;
            int r = lin >> 3, c = lin & 7;
            uint32_t so = st + r * 128 + ((c ^ (r & 7)) << 4);
            cpasync(so, (const char*)(AHb + (size_t)r * lda + kp) + (c << 4));
            cpasync(so + ABYTES, (const char*)(ALb + (size_t)r * lda + kp) + (c << 4));
        }
        // B fp32: 32KB, 8 x 16B chunks per thread into its own region
        const char* gsrc = BT
            ? (const char*)(Bb + (size_t)(kp + br) * ldb + n0)
            : (const char*)(Bb + (size_t)(n0 + br) * ldb + kp);
#pragma unroll
        for (int j = 0; j < 8; j++) {
            int inner = bq * 128 + j * 16;
            cpasync(st + BOFF + br * bROW + (inner ^ bsw), gsrc + inner);
        }
        CP_COMMIT();
    };

    issue(0);
    if (nslab > 1) issue(1);

    for (int s = 0; s < nslab; s++) {
        if (s + 2 < nslab) {
            issue(s + 2);
            asm volatile("cp.async.wait_group 2;" ::: "memory");
        } else if (s + 1 < nslab) {
            asm volatile("cp.async.wait_group 1;" ::: "memory");
        } else {
            asm volatile("cp.async.wait_group 0;" ::: "memory");
        }
        __syncthreads();

        const int stoff = (s % 3) * STAGE;
        const uint32_t st = sb + stoff;

        // ---- in-place convert of this thread's B region (read all, then write)
        {
            char* reg0 = sm + stoff + BOFF + br * bROW;
            float f[32];
#pragma unroll
            for (int j = 0; j < 8; j++) {
                int inner = bq * 128 + j * 16;
                float4 v = *(float4*)(reg0 + (inner ^ bsw));
                f[4 * j] = v.x; f[4 * j + 1] = v.y;
                f[4 * j + 2] = v.z; f[4 * j + 3] = v.w;
            }
#pragma unroll
            for (int m = 0; m < 4; m++) {
                uint32_t H[4], L[4];
#pragma unroll
                for (int i = 0; i < 4; i++)
                    cvt2(f[m * 8 + 2 * i], f[m * 8 + 2 * i + 1], H[i], L[i]);
                int innerH = bq * 128 + m * 16;
                *(uint4*)(reg0 + (innerH ^ bsw)) = make_uint4(H[0], H[1], H[2], H[3]);
                *(uint4*)(reg0 + ((innerH ^ bsw) + 64)) = make_uint4(L[0], L[1], L[2], L[3]);
            }
        }
        __syncthreads();

        // ---- mma over 4 k16 groups
#pragma unroll
        for (int kk = 0; kk < 4; kk++) {
            uint32_t aH[MS][4], aL[MS][4];
#pragma unroll
            for (int ms = 0; ms < MS; ms++) {
                int r = wm + ms * 16 + ((lane >> 3) & 1) * 8 + (lane & 7);
                int c = 2 * kk + (lane >> 4);
                uint32_t ad = st + r * 128 + ((c ^ (r & 7)) << 4);
                LDSM4(aH[ms], ad);
                LDSM4(aL[ms], ad + ABYTES);
            }
            uint32_t bH[NS][2], bL[NS][2];
#pragma unroll
            for (int j = 0; j < NS / 2; j++) {
                uint32_t t[4], u[4];
                if (BT) {
                    int r = kk * 16 + ((lane >> 3) & 1) * 8 + (lane & 7);
                    int c = (wn >> 3) + 2 * j + (lane >> 4);
                    int inner = (c >> 2) * 128 + (c & 3) * 16;
                    uint32_t ad = st + BOFF + r * 512 + (inner ^ ((r & 3) << 4));
                    LDSM4T(t, ad);
                    LDSM4T(u, ad + 64);
                } else {
                    int r = wn + j * 16 + ((lane >> 4) & 1) * 8 + (lane & 7);
                    int c = 2 * kk + ((lane >> 3) & 1);
                    int inner = (c >> 2) * 128 + (c & 3) * 16;
                    uint32_t ad = st + BOFF + r * 256 + (inner ^ ((r & 3) << 4));
                    LDSM4(t, ad);
                    LDSM4(u, ad + 64);
                }
                bH[2 * j][0] = t[0]; bH[2 * j][1] = t[1];
                bH[2 * j + 1][0] = t[2]; bH[2 * j + 1][1] = t[3];
                bL[2 * j][0] = u[0]; bL[2 * j][1] = u[1];
                bL[2 * j + 1][0] = u[2]; bL[2 * j + 1][1] = u[3];
            }
#pragma unroll
            for (int ns = 0; ns < NS; ns++) {
#pragma unroll
                for (int ms = 0; ms < MS; ms++) {
                    mma_bf16(acc[ms][ns], aH[ms], bH[ns]);
                    mma_bf16(acc[ms][ns], aH[ms], bL[ns]);
                    mma_bf16(acc[ms][ns], aL[ms], bH[ns]);
                }
            }
        }
        __syncthreads();
    }

#pragma unroll
    for (int ms = 0; ms < MS; ms++) {
#pragma unroll
        for (int ns = 0; ns < NS; ns++) {
            int r = wm + ms * 16 + (lane >> 2);
            int c = n0 + wn + ns * 8 + (lane & 3) * 2;
            float v0 = acc[ms][ns][0] * alpha, v1 = acc[ms][ns][1] * alpha;
            float v2 = acc[ms][ns][2] * alpha, v3 = acc[ms][ns][3] * alpha;
            if (AT) {
                atomicAdd(&Cb[(size_t)r * ldc + c], v0);
                atomicAdd(&Cb[(size_t)r * ldc + c + 1], v1);
                atomicAdd(&Cb[(size_t)(r + 8) * ldc + c], v2);
                atomicAdd(&Cb[(size_t)(r + 8) * ldc + c + 1], v3);
            } else {
                float2 p0 = {v0, v1}, p1 = {v2, v3};
                *(float2*)&Cb[(size_t)r * ldc + c] = p0;
                *(float2*)&Cb[(size_t)(r + 8) * ldc + c] = p1;
            }
        }
    }
}

// ---------------------------------------------------------------------------
__global__ void cvt_plane(const float4* __restrict__ X, uint2* __restrict__ H,
                          uint2* __restrict__ L, int n4)
{
    int i = blockIdx.x * 256 + threadIdx.x;
    int stride = gridDim.x * 256;
    for (; i < n4; i += stride) {
        float4 v = X[i];
        uint32_t h0, l0, h1, l1;
        cvt2(v.x, v.y, h0, l0);
        cvt2(v.z, v.w, h1, l1);
        H[i] = make_uint2(h0, h1);
        L[i] = make_uint2(l0, l1);
    }
}

__global__ void zero_k(float* __restrict__ p, int n) {
    int i = blockIdx.x * 256 + threadIdx.x;
    if (i < n) p[i] = 0.0f;
}

// rmsnorm: fp32 in -> bf16 hi/lo planes out
__global__ __launch_bounds__(256) void rmsnorm_k(
    const float* __restrict__ X, const float* __restrict__ W,
    __nv_bfloat16* __restrict__ YH, __nv_bfloat16* __restrict__ YL)
{
    __shared__ float red[32];
    int b = blockIdx.x, t = threadIdx.x;
    const float* x = X + b * QLR;
    float s = 0.0f;
    for (int i = t; i < QLR; i += 256) { float v = x[i]; s += v * v; }
    for (int o = 16; o > 0; o >>= 1) s += __shfl_xor_sync(~0u, s, o);
    if ((t & 31) == 0) red[t >> 5] = s;
    __syncthreads();
    if (t < 32) {
        float v = (t < 8) ? red[t] : 0.0f;
        for (int o = 4; o > 0; o >>= 1) v += __shfl_xor_sync(~0u, v, o);
        if (t == 0) red[0] = v;
    }
    __syncthreads();
    float r = rsqrtf(red[0] / (float)QLR + 1e-6f);
    for (int i = t * 2; i < QLR; i += 512) {
        float y0 = x[i] * r * W[i];
        float y1 = x[i + 1] * r * W[i + 1];
        uint32_t H, L;
        cvt2(y0, y1, H, L);
        *(uint32_t*)(YH + b * QLR + i) = H;
        *(uint32_t*)(YL + b * QLR + i) = L;
    }
}

__global__ void rope_k(const float* __restrict__ Q, const int* __restrict__ pos,
                       float* __restrict__ QY, float scale)
{
    int bh = blockIdx.x;
    int b = bh >> 7, h = bh & 127;
    int i = threadIdx.x;
    int j = i & 31;
    float p = (float)pos[b];
    float invf = powf(10000.0f, -(float)j / 32.0f);
    float s, c;
    sincosf(p * invf, &s, &c);
    const float* q = Q + (size_t)b * NH * QHD + h * QHD + 128;
    float v;
    if (i < 32) v = q[2 * j] * c - q[2 * j + 1] * s;
    else        v = q[2 * j + 1] * c + q[2 * j] * s;
    QY[(size_t)b * NH * CKVD + h * CKVD + 512 + i] = v * scale;
}

// Row softmax over 4096: fp32 scores -> bf16 hi/lo prob planes.
__global__ __launch_bounds__(256) void softmax_k(
    const float* __restrict__ S, __nv_bfloat16* __restrict__ PH,
    __nv_bfloat16* __restrict__ PL)
{
    __shared__ float red[32];
    size_t base = (size_t)blockIdx.x * KVLEN;
    int t = threadIdx.x;
    float4 v[4];
    float mx = -1e30f;
#pragma unroll
    for (int i = 0; i < 4; i++) {
        v[i] = *(const float4*)(S + base + t * 4 + i * 1024);
        mx = fmaxf(mx, fmaxf(fmaxf(v[i].x, v[i].y), fmaxf(v[i].z, v[i].w)));
    }
    for (int o = 16; o > 0; o >>= 1) mx = fmaxf(mx, __shfl_xor_sync(~0u, mx, o));
    if ((t & 31) == 0) red[t >> 5] = mx;
    __syncthreads();
    if (t < 32) {
        float m2 = (t < 8) ? red[t] : -1e30f;
        for (int o = 4; o > 0; o >>= 1) m2 = fmaxf(m2, __shfl_xor_sync(~0u, m2, o));
        if (t == 0) red[0] = m2;
    }
    __syncthreads();
    mx = red[0];
    __syncthreads();
    float sum = 0.0f;
#pragma unroll
    for (int i = 0; i < 4; i++) {
        v[i].x = __expf(v[i].x - mx); v[i].y = __expf(v[i].y - mx);
        v[i].z = __expf(v[i].z - mx); v[i].w = __expf(v[i].w - mx);
        sum += v[i].x + v[i].y + v[i].z + v[i].w;
    }
    for (int o = 16; o > 0; o >>= 1) sum += __shfl_xor_sync(~0u, sum, o);
    if ((t & 31) == 0) red[t >> 5] = sum;
    __syncthreads();
    if (t < 32) {
        float s2 = (t < 8) ? red[t] : 0.0f;
        for (int o = 4; o > 0; o >>= 1) s2 += __shfl_xor_sync(~0u, s2, o);
        if (t == 0) red[0] = s2;
    }
    __syncthreads();
    float inv = 1.0f / red[0];
#pragma unroll
    for (int i = 0; i < 4; i++) {
        float a = v[i].x * inv, bq = v[i].y * inv;
        float cc = v[i].z * inv, d = v[i].w * inv;
        uint32_t h0, l0, h1, l1;
        cvt2(a, bq, h0, l0);
        cvt2(cc, d, h1, l1);
        size_t idx = base + t * 4 + i * 1024;
        *(uint2*)(PH + idx) = make_uint2(h0, h1);
        *(uint2*)(PL + idx) = make_uint2(l0, l1);
    }
}

// ---------------------------------------------------------------------------
extern "C" void kernel_launch(void* const* d_in, const int* in_sizes, int n_in,
                              void* d_out, int out_size)
{
    const float* hq   = (const float*)d_in[0];
    const int*   pos  = (const int*)d_in[1];
    const float* ckv  = (const float*)d_in[2];
    const float* Wqa  = (const float*)d_in[3];
    const float* lnw  = (const float*)d_in[4];
    const float* Wqb  = (const float*)d_in[5];
    const float* Wkvb = (const float*)d_in[6];
    const float* Wo   = (const float*)d_in[7];
    float* out = (float*)d_out;

    float *qa, *q, *qry, *sc, *at, *o;
    __nv_bfloat16 *hqH, *hqL, *qanH, *qanL, *qH, *qL, *qryH, *qryL;
    __nv_bfloat16 *prH, *prL, *atH, *atL, *oH, *oL;
    cudaGetSymbolAddress((void**)&qa,   g_qa);
    cudaGetSymbolAddress((void**)&q,    g_q);
    cudaGetSymbolAddress((void**)&qry,  g_query);
    cudaGetSymbolAddress((void**)&sc,   g_scores);
    cudaGetSymbolAddress((void**)&at,   g_attn);
    cudaGetSymbolAddress((void**)&o,    g_o);
    cudaGetSymbolAddress((void**)&hqH,  g_hqH);
    cudaGetSymbolAddress((void**)&hqL,  g_hqL);
    cudaGetSymbolAddress((void**)&qanH, g_qanH);
    cudaGetSymbolAddress((void**)&qanL, g_qanL);
    cudaGetSymbolAddress((void**)&qH,   g_qH);
    cudaGetSymbolAddress((void**)&qL,   g_qL);
    cudaGetSymbolAddress((void**)&qryH, g_qryH);
    cudaGetSymbolAddress((void**)&qryL, g_qryL);
    cudaGetSymbolAddress((void**)&prH,  g_prH);
    cudaGetSymbolAddress((void**)&prL,  g_prL);
    cudaGetSymbolAddress((void**)&atH,  g_atH);
    cudaGetSymbolAddress((void**)&atL,  g_atL);
    cudaGetSymbolAddress((void**)&oH,   g_oH);
    cudaGetSymbolAddress((void**)&oL,   g_oL);

    const int SM32  = 3 * (32 * 256 + 32768);    // 122880
    const int SM128 = 3 * (128 * 256 + 32768);   // 196608
    cudaFuncSetAttribute(cgemm<32,  false, true>,
                         cudaFuncAttributeMaxDynamicSharedMemorySize, SM32);
    cudaFuncSetAttribute(cgemm<32,  true,  false>,
                         cudaFuncAttributeMaxDynamicSharedMemorySize, SM32);
    cudaFuncSetAttribute(cgemm<128, false, false>,
                         cudaFuncAttributeMaxDynamicSharedMemorySize, SM128);
    cudaFuncSetAttribute(cgemm<128, true,  true>,
                         cudaFuncAttributeMaxDynamicSharedMemorySize, SM128);

    const float scale = 1.0f / sqrtf(192.0f);

    // activation planes for first GEMM's A
    cvt_plane<<<160, 256>>>((const float4*)hq, (uint2*)hqH, (uint2*)hqL,
                            NB * HID / 4);

    // zero atomic destinations
    zero_k<<<192, 256>>>(qa, NB * QLR);
    zero_k<<<640, 256>>>(out, NB * HID);
    zero_k<<<3072, 256>>>(q, NB * NH * QHD);
    zero_k<<<2048, 256>>>(o, NB * NH * 128);
    zero_k<<<8192, 256>>>(at, NB * NH * KVLR);

    // q_a = hq @ Wq_a^T : M=32, N=1536, K=5120, split-K=20
    cgemm<32, false, true><<<dim3(12, 1, 20), 256, SM32>>>(
        hqH, hqL, HID, 0, Wqa, HID, 0, qa, QLR, 0, HID, 1.0f);

    rmsnorm_k<<<32, 256>>>(qa, lnw, qanH, qanL);

    // q = qan @ Wq_b^T : M=32, N=24576, K=1536, split-K=2
    cgemm<32, false, true><<<dim3(192, 1, 2), 256, SM32>>>(
        qanH, qanL, QLR, 0, Wqb, QLR, 0, q, NH * QHD, 0, QLR, 1.0f);

    // RoPE -> query[..., 512:576] (scaled)
    rope_k<<<NB * NH, 64>>>(q, pos, qry, scale);

    // q planes (for q_lat A)
    cvt_plane<<<768, 256>>>((const float4*)q, (uint2*)qH, (uint2*)qL,
                            NB * NH * QHD / 4);

    // q_lat: per head M=32, N=512, K=128 (NN vs q_absorb) -> query[..., :512]
    cgemm<32, true, false><<<dim3(4, NH, 1), 256, SM32>>>(
        qH, qL, NH * QHD, QHD,
        Wkvb, KVLR, 256 * KVLR,
        qry, NH * CKVD, CKVD,
        128, scale);

    // query planes
    cvt_plane<<<2304, 256>>>((const float4*)qry, (uint2*)qryH, (uint2*)qryL,
                             NB * NH * CKVD / 4);

    // scores: per b [128 heads] x [4096 kv], K=576 (NT vs fp32 ckv)
    cgemm<128, false, false><<<dim3(32, NB, 1), 256, SM128>>>(
        qryH, qryL, CKVD, NH * CKVD,
        ckv, CKVD, KVLEN * CKVD,
        sc, KVLEN, NH * KVLEN,
        CKVD, 1.0f);

    softmax_k<<<NB * NH, 256>>>(sc, prH, prL);

    // attn: per b [128 heads] x [512 lat], K=4096 (NN vs fp32 ckv), split-K=4
    cgemm<128, true, true><<<dim3(4, NB, 4), 256, SM128>>>(
        prH, prL, KVLEN, NH * KVLEN,
        ckv, CKVD, KVLEN * CKVD,
        at, KVLR, NH * KVLR,
        KVLEN, 1.0f);

    // attn planes
    cvt_plane<<<2048, 256>>>((const float4*)at, (uint2*)atH, (uint2*)atL,
                             NB * NH * KVLR / 4);

    // o: per head M=32, N=128, K=512 (NT vs out_absorb), split-K=4
    cgemm<32, false, true><<<dim3(1, NH, 4), 256, SM32>>>(
        atH, atL, NH * KVLR, KVLR,
        Wkvb + 128 * KVLR, KVLR, 256 * KVLR,
        o, NH * 128, 128,
        KVLR, 1.0f);

    // o planes
    cvt_plane<<<512, 256>>>((const float4*)o, (uint2*)oH, (uint2*)oL,
                            NB * NH * 128 / 4);

    // out = o @ Wo^T : M=32, N=5120, K=16384, split-K=16
    cgemm<32, false, true><<<dim3(40, 1, 16), 256, SM32>>>(
        oH, oL, NH * 128, 0, Wo, NH * 128, 0, out, HID, 0, NH * 128, 1.0f);
}

// round 16
// speedup vs baseline: 1.2752x; 1.2752x over previous
#include <cuda_runtime.h>
#include <cuda_bf16.h>
#include <math.h>
#include <stdint.h>

#define NB 32
#define NH 128
#define HID 5120
#define QLR 1536
#define KVLR 512
#define KVLEN 4096
#define CKVD 576
#define QHD 192

// ----------------------- device scratch (no allocs allowed) -----------------
__device__ __align__(16) float g_qa[NB * QLR];
__device__ __align__(16) float g_qan[NB * QLR];
__device__ __align__(16) float g_q[NB * NH * QHD];
__device__ __align__(16) float g_query[NB * NH * CKVD];
__device__ __align__(16) float g_scores[(size_t)NB * NH * KVLEN];   // 64 MB
__device__ __align__(16) float g_attn[NB * NH * KVLR];
__device__ __align__(16) float g_o[NB * NH * 128];

__device__ __align__(16) __nv_bfloat16 g_ckvH[(size_t)NB * KVLEN * CKVD];  // 151 MB
__device__ __align__(16) __nv_bfloat16 g_ckvL[(size_t)NB * KVLEN * CKVD];  // 151 MB
__device__ __align__(16) __nv_bfloat16 g_qryH[NB * NH * CKVD];
__device__ __align__(16) __nv_bfloat16 g_qryL[NB * NH * CKVD];
__device__ __align__(16) __nv_bfloat16 g_prH[(size_t)NB * NH * KVLEN];
__device__ __align__(16) __nv_bfloat16 g_prL[(size_t)NB * NH * KVLEN];

// ----------------------- helpers -------------------------------------------
__device__ __forceinline__ uint32_t pkbf2(float a, float b) {
    __nv_bfloat162 t = __floats2bfloat162_rn(a, b);
    return *(uint32_t*)&t;
}
__device__ __forceinline__ float bfhi(float x) {
    return __bfloat162float(__float2bfloat16_rn(x));
}
__device__ __forceinline__ void mma_bf16(float* c, const uint32_t* a, const uint32_t* b) {
    asm volatile(
        "mma.sync.aligned.m16n8k16.row.col.f32.bf16.bf16.f32 "
        "{%0,%1,%2,%3},{%4,%5,%6,%7},{%8,%9},{%0,%1,%2,%3};\n"
        : "+f"(c[0]), "+f"(c[1]), "+f"(c[2]), "+f"(c[3])
        : "r"(a[0]), "r"(a[1]), "r"(a[2]), "r"(a[3]), "r"(b[0]), "r"(b[1]));
}
__device__ __forceinline__ void cvt2(float a, float b, uint32_t& H, uint32_t& L) {
    asm("cvt.rn.satfinite.bf16x2.f32 %0, %1, %2;" : "=r"(H) : "f"(b), "f"(a));
    float ha = __uint_as_float(H << 16);
    float hb = __uint_as_float(H & 0xffff0000u);
    asm("cvt.rn.satfinite.bf16x2.f32 %0, %1, %2;" : "=r"(L) : "f"(b - hb), "f"(a - ha));
}
__device__ __forceinline__ uint32_t smem_u32(const void* p) {
    uint32_t a;
    asm("{ .reg .u64 t; cvta.to.shared.u64 t, %1; cvt.u32.u64 %0, t; }"
        : "=r"(a) : "l"(p));
    return a;
}
__device__ __forceinline__ void cpasync(uint32_t s, const void* g) {
    asm volatile("cp.async.cg.shared.global [%0],[%1],16;" :: "r"(s), "l"(g) : "memory");
}
#define CP_COMMIT() asm volatile("cp.async.commit_group;" ::: "memory")
#define LDSM4(r, ad) \
    asm volatile("ldmatrix.sync.aligned.m8n8.x4.shared.b16 {%0,%1,%2,%3},[%4];" \
        : "=r"((r)[0]), "=r"((r)[1]), "=r"((r)[2]), "=r"((r)[3]) : "r"(ad))
#define LDSM4T(r, ad) \
    asm volatile("ldmatrix.sync.aligned.m8n8.x4.trans.shared.b16 {%0,%1,%2,%3},[%4];" \
        : "=r"((r)[0]), "=r"((r)[1]), "=r"((r)[2]), "=r"((r)[3]) : "r"(ad))

#define PIPE_SMEM 196608   /* 3 stages x 64KB */

// ---------------------------------------------------------------------------
// Pipelined bf16 hi/lo GEMM on pre-split planes (attention path, unchanged).
//   BT=false: B planes [n][k] (NT).  BT=true: B planes [k][n] (NN).
// CTA tile 128x128, KC=64, 256 threads, 3-stage cp.async pipeline.
// grid.x = N/128, grid.y = batch, grid.z = split-K (AT -> atomics).
// ---------------------------------------------------------------------------
template <bool BT, bool AT>
__global__ __launch_bounds__(256, 1) void pipegemm(
    const __nv_bfloat16* __restrict__ AH, const __nv_bfloat16* __restrict__ AL,
    int lda, int sA,
    const __nv_bfloat16* __restrict__ BH, const __nv_bfloat16* __restrict__ BL,
    int ldb, int sB,
    float* __restrict__ C, int ldc, int sC, int K)
{
    extern __shared__ __align__(1024) char sm[];
    const uint32_t sb = smem_u32(sm);
    const int tid = threadIdx.x, lane = tid & 31, warp = tid >> 5;
    const int b = blockIdx.y;
    const __nv_bfloat16* AHb = AH + (size_t)b * sA;
    const __nv_bfloat16* ALb = AL + (size_t)b * sA;
    const __nv_bfloat16* BHb = BH + (size_t)b * sB;
    const __nv_bfloat16* BLb = BL + (size_t)b * sB;
    float* Cb = C + (size_t)b * sC;
    const int n0 = blockIdx.x * 128;
    const int kseg = K / (int)gridDim.z;
    const int kst = blockIdx.z * kseg;
    const int nslab = kseg >> 6;

    const int wm = (warp >> 1) * 32;
    const int wn = (warp & 1) * 64;

    float acc[2][8][4];
#pragma unroll
    for (int i = 0; i < 2; i++)
#pragma unroll
        for (int j = 0; j < 8; j++)
#pragma unroll
            for (int q = 0; q < 4; q++) acc[i][j][q] = 0.0f;

    auto issue = [&](int s) {
        const int kp = kst + s * 64;
        const uint32_t st = sb + (s % 3) * 65536;
#pragma unroll
        for (int i = 0; i < 4; i++) {
            int lin = tid + i * 256;
            int r = lin >> 3, c = lin & 7;
            uint32_t so = st + r * 128 + ((c ^ (r & 7)) << 4);
            const char* gh = (const char*)(AHb + (size_t)r * lda + kp) + (c << 4);
            const char* gl = (const char*)(ALb + (size_t)r * lda + kp) + (c << 4);
            cpasync(so, gh);
            cpasync(so + 16384, gl);
        }
        if (BT) {
#pragma unroll
            for (int i = 0; i < 4; i++) {
                int lin = tid + i * 256;
                int r = lin >> 4, c = lin & 15;
                uint32_t so = st + 32768 + r * 256 + ((c ^ (r & 7)) << 4);
                const char* gh = (const char*)(BHb + (size_t)(kp + r) * ldb + n0) + (c << 4);
                const char* gl = (const char*)(BLb + (size_t)(kp + r) * ldb + n0) + (c << 4);
                cpasync(so, gh);
                cpasync(so + 16384, gl);
            }
        } else {
#pragma unroll
            for (int i = 0; i < 4; i++) {
                int lin = tid + i * 256;
                int r = lin >> 3, c = lin & 7;
                uint32_t so = st + 32768 + r * 128 + ((c ^ (r & 7)) << 4);
                const char* gh = (const char*)(BHb + (size_t)(n0 + r) * ldb + kp) + (c << 4);
                const char* gl = (const char*)(BLb + (size_t)(n0 + r) * ldb + kp) + (c << 4);
                cpasync(so, gh);
                cpasync(so + 16384, gl);
            }
        }
        CP_COMMIT();
    };

    issue(0);
    if (nslab > 1) issue(1);

    for (int s = 0; s < nslab; s++) {
        if (s + 2 < nslab) {
            issue(s + 2);
            asm volatile("cp.async.wait_group 2;" ::: "memory");
        } else if (s + 1 < nslab) {
            asm volatile("cp.async.wait_group 1;" ::: "memory");
        } else {
            asm volatile("cp.async.wait_group 0;" ::: "memory");
        }
        __syncthreads();
        const uint32_t st = sb + (s % 3) * 65536;

#pragma unroll
        for (int kk = 0; kk < 4; kk++) {
            uint32_t aH[2][4], aL[2][4];
#pragma unroll
            for (int ms = 0; ms < 2; ms++) {
                int r = wm + ms * 16 + ((lane >> 3) & 1) * 8 + (lane & 7);
                int c = 2 * kk + (lane >> 4);
                uint32_t ad = st + r * 128 + ((c ^ (r & 7)) << 4);
                LDSM4(aH[ms], ad);
                LDSM4(aL[ms], ad + 16384);
            }
            uint32_t bH[8][2], bL[8][2];
            if (BT) {
#pragma unroll
                for (int j = 0; j < 4; j++) {
                    int r = kk * 16 + ((lane >> 3) & 1) * 8 + (lane & 7);
                    int c = (wn >> 3) + 2 * j + (lane >> 4);
                    uint32_t ad = st + 32768 + r * 256 + ((c ^ (r & 7)) << 4);
                    uint32_t t[4], u[4];
                    LDSM4T(t, ad);
                    LDSM4T(u, ad + 16384);
                    bH[2 * j][0] = t[0]; bH[2 * j][1] = t[1];
                    bH[2 * j + 1][0] = t[2]; bH[2 * j + 1][1] = t[3];
                    bL[2 * j][0] = u[0]; bL[2 * j][1] = u[1];
                    bL[2 * j + 1][0] = u[2]; bL[2 * j + 1][1] = u[3];
                }
            } else {
#pragma unroll
                for (int j = 0; j < 4; j++) {
                    int r = wn + j * 16 + ((lane >> 4) & 1) * 8 + (lane & 7);
                    int c = 2 * kk + ((lane >> 3) & 1);
                    uint32_t ad = st + 32768 + r * 128 + ((c ^ (r & 7)) << 4);
                    uint32_t t[4], u[4];
                    LDSM4(t, ad);
                    LDSM4(u, ad + 16384);
                    bH[2 * j][0] = t[0]; bH[2 * j][1] = t[1];
                    bH[2 * j + 1][0] = t[2]; bH[2 * j + 1][1] = t[3];
                    bL[2 * j][0] = u[0]; bL[2 * j][1] = u[1];
                    bL[2 * j + 1][0] = u[2]; bL[2 * j + 1][1] = u[3];
                }
            }
#pragma unroll
            for (int ns = 0; ns < 8; ns++) {
#pragma unroll
                for (int ms = 0; ms < 2; ms++) {
                    mma_bf16(acc[ms][ns], aH[ms], bH[ns]);
                    mma_bf16(acc[ms][ns], aH[ms], bL[ns]);
                    mma_bf16(acc[ms][ns], aL[ms], bH[ns]);
                }
            }
        }
        __syncthreads();
    }

#pragma unroll
    for (int ms = 0; ms < 2; ms++) {
#pragma unroll
        for (int ns = 0; ns < 8; ns++) {
            int r = wm + ms * 16 + (lane >> 2);
            int c = n0 + wn + ns * 8 + (lane & 3) * 2;
            if (AT) {
                atomicAdd(&Cb[(size_t)r * ldc + c], acc[ms][ns][0]);
                atomicAdd(&Cb[(size_t)r * ldc + c + 1], acc[ms][ns][1]);
                atomicAdd(&Cb[(size_t)(r + 8) * ldc + c], acc[ms][ns][2]);
                atomicAdd(&Cb[(size_t)(r + 8) * ldc + c + 1], acc[ms][ns][3]);
            } else {
                float2 p0 = {acc[ms][ns][0], acc[ms][ns][1]};
                float2 p1 = {acc[ms][ns][2], acc[ms][ns][3]};
                *(float2*)&Cb[(size_t)r * ldc + c] = p0;
                *(float2*)&Cb[(size_t)(r + 8) * ldc + c] = p1;
            }
        }
    }
}

// ---------------------------------------------------------------------------
__global__ void cvt_plane(const float4* __restrict__ X, uint2* __restrict__ H,
                          uint2* __restrict__ L, int n4)
{
    int i = blockIdx.x * 256 + threadIdx.x;
    int stride = gridDim.x * 256;
    for (; i < n4; i += stride) {
        float4 v = X[i];
        uint32_t h0, l0, h1, l1;
        cvt2(v.x, v.y, h0, l0);
        cvt2(v.z, v.w, h1, l1);
        H[i] = make_uint2(h0, h1);
        L[i] = make_uint2(l0, l1);
    }
}

// ---------------------------------------------------------------------------
// mma.sync GEMM for M=32 weight GEMMs; KC=64 (deeper prefetch, fewer syncs)
// ---------------------------------------------------------------------------
template <bool BNN, bool ATOMIC>
__global__ __launch_bounds__(256, 2) void mmagemm(
    const float* __restrict__ A, int lda, int sA,
    const float* __restrict__ B, int ldb, int sB,
    float* __restrict__ C, int ldc, int sC,
    int K, float alpha)
{
    constexpr int KC = 64;
    constexpr int MS = 1, NS = 4;

    __shared__ __align__(16) __nv_bfloat16 AsH[32][KC + 2];
    __shared__ __align__(16) __nv_bfloat16 AsL[32][KC + 2];
    __shared__ __align__(16) __nv_bfloat16 BsH[128][KC + 2];
    __shared__ __align__(16) __nv_bfloat16 BsL[128][KC + 2];
    constexpr int BPITCH = (KC + 2) * 2;   // bytes per Bs row = 132

    const float* Ab = A + (size_t)blockIdx.z * sA;
    const float* Bb = B + (size_t)blockIdx.z * sB;
    float* Cb = C + (size_t)blockIdx.z * sC;

    const int n0 = blockIdx.x * 128;
    const int kseg = K / (int)gridDim.y;
    const int kst = blockIdx.y * kseg;

    const int tid = threadIdx.x;
    const int lane = tid & 31;
    const int warp = tid >> 5;
    const int wm = (warp & 1) * 16;
    const int wn = (warp >> 1) * 32;
    const int fr = lane >> 2;
    const int fc = (lane & 3) * 2;

    float acc[MS][NS][4];
#pragma unroll
    for (int i = 0; i < MS; i++)
#pragma unroll
        for (int j = 0; j < NS; j++)
#pragma unroll
            for (int q = 0; q < 4; q++) acc[i][j][q] = 0.0f;

    float4 pa[2];
    float4 pbt[8];
    float4 pb0[4], pb1[4];

    auto loadA = [&](int kp) {
#pragma unroll
        for (int i = 0; i < 2; i++) {
            int lin = tid + i * 256;
            int r = lin >> 4, k4 = (lin & 15) * 4;
            pa[i] = *(const float4*)(Ab + (size_t)r * lda + kp + k4);
        }
    };
    auto storeA = [&]() {
#pragma unroll
        for (int i = 0; i < 2; i++) {
            int lin = tid + i * 256;
            int r = lin >> 4, k4 = (lin & 15) * 4;
            float4 v = pa[i];
            float hx = bfhi(v.x), hy = bfhi(v.y), hz = bfhi(v.z), hw = bfhi(v.w);
            uint32_t* dh = (uint32_t*)&AsH[r][k4];
            uint32_t* dl = (uint32_t*)&AsL[r][k4];
            dh[0] = pkbf2(hx, hy); dh[1] = pkbf2(hz, hw);
            dl[0] = pkbf2(v.x - hx, v.y - hy); dl[1] = pkbf2(v.z - hz, v.w - hw);
        }
    };
    auto loadB = [&](int kp) {
        if (BNN) {
#pragma unroll
            for (int g = 0; g < 4; g++) {
                int slot = tid + g * 256;
                int kpp = slot >> 5;              // 0..31 k-pairs
                int n = (slot & 31) * 4;
                const float* r0 = Bb + (size_t)(kp + 2 * kpp) * ldb + n0 + n;
                pb0[g] = *(const float4*)r0;
                pb1[g] = *(const float4*)(r0 + ldb);
            }
        } else {
#pragma unroll
            for (int i = 0; i < 8; i++) {
                int lin = tid + i * 256;
                int nr = lin >> 4, k4 = (lin & 15) * 4;
                pbt[i] = *(const float4*)(Bb + (size_t)(n0 + nr) * ldb + kp + k4);
            }
        }
    };
    auto storeB = [&]() {
        if (BNN) {
#pragma unroll
            for (int g = 0; g < 4; g++) {
                int slot = tid + g * 256;
                int kpp = slot >> 5;
                int n = (slot & 31) * 4;
                float r0[4] = {pb0[g].x, pb0[g].y, pb0[g].z, pb0[g].w};
                float r1[4] = {pb1[g].x, pb1[g].y, pb1[g].z, pb1[g].w};
#pragma unroll
                for (int j = 0; j < 4; j++) {
                    int nn = n + j;
                    int w = kpp ^ ((nn >> 3) & 15);
                    float h0 = bfhi(r0[j]), h1 = bfhi(r1[j]);
                    *(uint32_t*)((char*)&BsH[0][0] + nn * BPITCH + 4 * w) = pkbf2(h0, h1);
                    *(uint32_t*)((char*)&BsL[0][0] + nn * BPITCH + 4 * w) =
                        pkbf2(r0[j] - h0, r1[j] - h1);
                }
            }
        } else {
#pragma unroll
            for (int i = 0; i < 8; i++) {
                int lin = tid + i * 256;
                int nr = lin >> 4, k4 = (lin & 15) * 4;
                float4 v = pbt[i];
                float hx = bfhi(v.x), hy = bfhi(v.y), hz = bfhi(v.z), hw = bfhi(v.w);
                uint32_t* dh = (uint32_t*)&BsH[nr][k4];
                uint32_t* dl = (uint32_t*)&BsL[nr][k4];
                dh[0] = pkbf2(hx, hy); dh[1] = pkbf2(hz, hw);
                dl[0] = pkbf2(v.x - hx, v.y - hy); dl[1] = pkbf2(v.z - hz, v.w - hw);
            }
        }
    };

    loadA(kst);
    loadB(kst);

    const int kend = kst + kseg;
    for (int kp = kst; kp < kend; kp += KC) {
        __syncthreads();
        storeA();
        storeB();
        __syncthreads();
        if (kp + KC < kend) { loadA(kp + KC); loadB(kp + KC); }

#pragma unroll
        for (int k16 = 0; k16 < KC; k16 += 16) {
            uint32_t aH[MS][4], aL[MS][4];
#pragma unroll
            for (int ms = 0; ms < MS; ms++) {
                int ra = wm + ms * 16 + fr;
                aH[ms][0] = *(uint32_t*)&AsH[ra][k16 + fc];
                aH[ms][1] = *(uint32_t*)&AsH[ra + 8][k16 + fc];
                aH[ms][2] = *(uint32_t*)&AsH[ra][k16 + fc + 8];
                aH[ms][3] = *(uint32_t*)&AsH[ra + 8][k16 + fc + 8];
                aL[ms][0] = *(uint32_t*)&AsL[ra][k16 + fc];
                aL[ms][1] = *(uint32_t*)&AsL[ra + 8][k16 + fc];
                aL[ms][2] = *(uint32_t*)&AsL[ra][k16 + fc + 8];
                aL[ms][3] = *(uint32_t*)&AsL[ra + 8][k16 + fc + 8];
            }
#pragma unroll
            for (int ns = 0; ns < NS; ns++) {
                int cB = wn + ns * 8 + fr;
                int w0 = (k16 >> 1) + (lane & 3);
                int w1 = w0 + 4;
                if (BNN) {
                    int s2 = (cB >> 3) & 15;
                    w0 ^= s2; w1 ^= s2;
                }
                uint32_t bH[2], bL[2];
                bH[0] = *(uint32_t*)((char*)&BsH[0][0] + cB * BPITCH + 4 * w0);
                bH[1] = *(uint32_t*)((char*)&BsH[0][0] + cB * BPITCH + 4 * w1);
                bL[0] = *(uint32_t*)((char*)&BsL[0][0] + cB * BPITCH + 4 * w0);
                bL[1] = *(uint32_t*)((char*)&BsL[0][0] + cB * BPITCH + 4 * w1);
#pragma unroll
                for (int ms = 0; ms < MS; ms++) {
                    mma_bf16(acc[ms][ns], aH[ms], bH);
                    mma_bf16(acc[ms][ns], aH[ms], bL);
                    mma_bf16(acc[ms][ns], aL[ms], bH);
                }
            }
        }
    }

#pragma unroll
    for (int ms = 0; ms < MS; ms++) {
#pragma unroll
        for (int ns = 0; ns < NS; ns++) {
            int cr = wm + ms * 16 + fr;
            int cc = n0 + wn + ns * 8 + (lane & 3) * 2;
            float v0 = acc[ms][ns][0] * alpha, v1 = acc[ms][ns][1] * alpha;
            float v2 = acc[ms][ns][2] * alpha, v3 = acc[ms][ns][3] * alpha;
            if (ATOMIC) {
                atomicAdd(&Cb[(size_t)cr * ldc + cc], v0);
                atomicAdd(&Cb[(size_t)cr * ldc + cc + 1], v1);
                atomicAdd(&Cb[(size_t)(cr + 8) * ldc + cc], v2);
                atomicAdd(&Cb[(size_t)(cr + 8) * ldc + cc + 1], v3);
            } else {
                float2 p0 = {v0, v1}, p1 = {v2, v3};
                *(float2*)&Cb[(size_t)cr * ldc + cc] = p0;
                *(float2*)&Cb[(size_t)(cr + 8) * ldc + cc] = p1;
            }
        }
    }
}

// ---------------------------------------------------------------------------
__global__ void zero_all(float* p0, int n0, float* p1, int n1, float* p2, int n2,
                         float* p3, int n3, float* p4, int n4)
{
    int i = blockIdx.x * 256 + threadIdx.x;
    int stride = gridDim.x * 256;
    for (int j = i; j < n0; j += stride) p0[j] = 0.0f;
    for (int j = i; j < n1; j += stride) p1[j] = 0.0f;
    for (int j = i; j < n2; j += stride) p2[j] = 0.0f;
    for (int j = i; j < n3; j += stride) p3[j] = 0.0f;
    for (int j = i; j < n4; j += stride) p4[j] = 0.0f;
}

__global__ __launch_bounds__(256) void rmsnorm_k(
    const float* __restrict__ X, const float* __restrict__ W, float* __restrict__ Y)
{
    __shared__ float red[32];
    int b = blockIdx.x, t = threadIdx.x;
    const float* x = X + b * QLR;
    float s = 0.0f;
    for (int i = t; i < QLR; i += 256) { float v = x[i]; s += v * v; }
    for (int o = 16; o > 0; o >>= 1) s += __shfl_xor_sync(~0u, s, o);
    if ((t & 31) == 0) red[t >> 5] = s;
    __syncthreads();
    if (t < 32) {
        float v = (t < 8) ? red[t] : 0.0f;
        for (int o = 4; o > 0; o >>= 1) v += __shfl_xor_sync(~0u, v, o);
        if (t == 0) red[0] = v;
    }
    __syncthreads();
    float r = rsqrtf(red[0] / (float)QLR + 1e-6f);
    for (int i = t; i < QLR; i += 256) Y[b * QLR + i] = x[i] * r * W[i];
}

__global__ void rope_k(const float* __restrict__ Q, const int* __restrict__ pos,
                       float* __restrict__ QY, float scale)
{
    int bh = blockIdx.x;
    int b = bh >> 7, h = bh & 127;
    int i = threadIdx.x;
    int j = i & 31;
    float p = (float)pos[b];
    float invf = powf(10000.0f, -(float)j / 32.0f);
    float s, c;
    sincosf(p * invf, &s, &c);
    const float* q = Q + (size_t)b * NH * QHD + h * QHD + 128;
    float v;
    if (i < 32) v = q[2 * j] * c - q[2 * j + 1] * s;
    else        v = q[2 * j + 1] * c + q[2 * j] * s;
    QY[(size_t)b * NH * CKVD + h * CKVD + 512 + i] = v * scale;
}

// Row softmax over 4096: fp32 scores -> bf16 hi/lo prob planes.
__global__ __launch_bounds__(256) void softmax_k(
    const float* __restrict__ S, __nv_bfloat16* __restrict__ PH,
    __nv_bfloat16* __restrict__ PL)
{
    __shared__ float red[32];
    size_t base = (size_t)blockIdx.x * KVLEN;
    int t = threadIdx.x;
    float4 v[4];
    float mx = -1e30f;
#pragma unroll
    for (int i = 0; i < 4; i++) {
        v[i] = *(const float4*)(S + base + t * 4 + i * 1024);
        mx = fmaxf(mx, fmaxf(fmaxf(v[i].x, v[i].y), fmaxf(v[i].z, v[i].w)));
    }
    for (int o = 16; o > 0; o >>= 1) mx = fmaxf(mx, __shfl_xor_sync(~0u, mx, o));
    if ((t & 31) == 0) red[t >> 5] = mx;
    __syncthreads();
    if (t < 32) {
        float m2 = (t < 8) ? red[t] : -1e30f;
        for (int o = 4; o > 0; o >>= 1) m2 = fmaxf(m2, __shfl_xor_sync(~0u, m2, o));
        if (t == 0) red[0] = m2;
    }
    __syncthreads();
    mx = red[0];
    __syncthreads();
    float sum = 0.0f;
#pragma unroll
    for (int i = 0; i < 4; i++) {
        v[i].x = __expf(v[i].x - mx); v[i].y = __expf(v[i].y - mx);
        v[i].z = __expf(v[i].z - mx); v[i].w = __expf(v[i].w - mx);
        sum += v[i].x + v[i].y + v[i].z + v[i].w;
    }
    for (int o = 16; o > 0; o >>= 1) sum += __shfl_xor_sync(~0u, sum, o);
    if ((t & 31) == 0) red[t >> 5] = sum;
    __syncthreads();
    if (t < 32) {
        float s2 = (t < 8) ? red[t] : 0.0f;
        for (int o = 4; o > 0; o >>= 1) s2 += __shfl_xor_sync(~0u, s2, o);
        if (t == 0) red[0] = s2;
    }
    __syncthreads();
    float inv = 1.0f / red[0];
#pragma unroll
    for (int i = 0; i < 4; i++) {
        float a = v[i].x * inv, bq = v[i].y * inv;
        float cc = v[i].z * inv, d = v[i].w * inv;
        uint32_t h0, l0, h1, l1;
        cvt2(a, bq, h0, l0);
        cvt2(cc, d, h1, l1);
        size_t idx = base + t * 4 + i * 1024;
        *(uint2*)(PH + idx) = make_uint2(h0, h1);
        *(uint2*)(PL + idx) = make_uint2(l0, l1);
    }
}

// ---------------------------------------------------------------------------
extern "C" void kernel_launch(void* const* d_in, const int* in_sizes, int n_in,
                              void* d_out, int out_size)
{
    const float* hq   = (const float*)d_in[0];
    const int*   pos  = (const int*)d_in[1];
    const float* ckv  = (const float*)d_in[2];
    const float* Wqa  = (const float*)d_in[3];
    const float* lnw  = (const float*)d_in[4];
    const float* Wqb  = (const float*)d_in[5];
    const float* Wkvb = (const float*)d_in[6];
    const float* Wo   = (const float*)d_in[7];
    float* out = (float*)d_out;

    float *qa, *qan, *q, *qry, *sc, *at, *o;
    __nv_bfloat16 *ckvH, *ckvL, *qryH, *qryL, *prH, *prL;
    cudaGetSymbolAddress((void**)&qa,   g_qa);
    cudaGetSymbolAddress((void**)&qan,  g_qan);
    cudaGetSymbolAddress((void**)&q,    g_q);
    cudaGetSymbolAddress((void**)&qry,  g_query);
    cudaGetSymbolAddress((void**)&sc,   g_scores);
    cudaGetSymbolAddress((void**)&at,   g_attn);
    cudaGetSymbolAddress((void**)&o,    g_o);
    cudaGetSymbolAddress((void**)&ckvH, g_ckvH);
    cudaGetSymbolAddress((void**)&ckvL, g_ckvL);
    cudaGetSymbolAddress((void**)&qryH, g_qryH);
    cudaGetSymbolAddress((void**)&qryL, g_qryL);
    cudaGetSymbolAddress((void**)&prH,  g_prH);
    cudaGetSymbolAddress((void**)&prL,  g_prL);

    cudaFuncSetAttribute(pipegemm<false, false>,
                         cudaFuncAttributeMaxDynamicSharedMemorySize, PIPE_SMEM);
    cudaFuncSetAttribute(pipegemm<true, true>,
                         cudaFuncAttributeMaxDynamicSharedMemorySize, PIPE_SMEM);

    const float scale = 1.0f / sqrtf(192.0f);

    // 1: zero all atomic destinations (one launch)
    zero_all<<<2048, 256>>>(qa, NB * QLR, out, NB * HID, q, NB * NH * QHD,
                            o, NB * NH * 128, at, NB * NH * KVLR);

    // 2: q_a = hq @ Wq_a^T : M=32, N=1536, K=5120, split-K=20
    mmagemm<false, true><<<dim3(12, 20, 1), 256>>>(
        hq, HID, 0, Wqa, HID, 0, qa, QLR, 0, HID, 1.0f);

    // 3
    rmsnorm_k<<<32, 256>>>(qa, lnw, qan);

    // 4: q = qan @ Wq_b^T : M=32, N=24576, K=1536, split-K=3
    mmagemm<false, true><<<dim3(192, 3, 1), 256>>>(
        qan, QLR, 0, Wqb, QLR, 0, q, NH * QHD, 0, QLR, 1.0f);

    // 5: RoPE -> query[..., 512:576] (scaled)
    rope_k<<<NB * NH, 64>>>(q, pos, qry, scale);

    // 6: q_lat: per head M=32, N=512, K=128 (NN vs q_absorb)  [ncu sample]
    mmagemm<true, false><<<dim3(4, 1, NH), 256>>>(
        q, NH * QHD, QHD,
        Wkvb, KVLR, 256 * KVLR,
        qry, NH * CKVD, CKVD,
        128, scale);

    // 7: pre-split compressed_kv into bf16 hi/lo planes
    cvt_plane<<<36864, 256>>>((const float4*)ckv, (uint2*)ckvH, (uint2*)ckvL,
                              NB * KVLEN * CKVD / 4);

    // 8: split query into bf16 hi/lo planes
    cvt_plane<<<2304, 256>>>((const float4*)qry, (uint2*)qryH, (uint2*)qryL,
                             NB * NH * CKVD / 4);

    // 9: scores: per b [128 heads] x [4096 kv], K=576 — pipelined NT
    pipegemm<false, false><<<dim3(32, NB, 1), 256, PIPE_SMEM>>>(
        qryH, qryL, CKVD, NH * CKVD,
        ckvH, ckvL, CKVD, KVLEN * CKVD,
        sc, KVLEN, NH * KVLEN, CKVD);

    // 10: softmax -> bf16 hi/lo probs
    softmax_k<<<NB * NH, 256>>>(sc, prH, prL);

    // 11: attn: per b [128 heads] x [512 lat], K=4096 — pipelined NN, split-K=4
    pipegemm<true, true><<<dim3(4, NB, 4), 256, PIPE_SMEM>>>(
        prH, prL, KVLEN, NH * KVLEN,
        ckvH, ckvL, CKVD, KVLEN * CKVD,
        at, KVLR, NH * KVLR, KVLEN);

    // 12: o: per head M=32, N=128, K=512 (NT vs out_absorb), split-K=4
    mmagemm<false, true><<<dim3(1, 4, NH), 256>>>(
        at, NH * KVLR, KVLR,
        Wkvb + 128 * KVLR, KVLR, 256 * KVLR,
        o, NH * 128, 128,
        KVLR, 1.0f);

    // 13: out = o @ Wo^T : M=32, N=5120, K=16384, split-K=16
    mmagemm<false, true><<<dim3(40, 16, 1), 256>>>(
        o, NH * 128, 0, Wo, NH * 128, 0, out, HID, 0, NH * 128, 1.0f);
}